// round 15
// baseline (speedup 1.0000x reference)
#include <cuda_runtime.h>
#include <cuda_fp16.h>
#include <math.h>
#include <stdint.h>

// ---------------- problem constants ----------------
constexpr int B    = 2;
constexpr int CIN  = 192;
constexpr int CMID = 180;
constexpr int Hh   = 96;
constexpr int Ww   = 96;
constexpr int HW   = Hh * Ww;          // 9216
constexpr int KK   = 9;
constexpr int G    = 10;
constexpr int CG   = CMID / G;         // 18
constexpr int KDIM_P = 1664;           // 26 chunks of 64

constexpr size_t FSTR = (size_t)192 * HW;      // feature stride
constexpr size_t OSTR = (size_t)360 * HW;      // offs stride
constexpr size_t CSTR = (size_t)KDIM_P * HW;   // col plane stride
constexpr int    XDE  = HW + 2;                // xrd entries per quad (+pad)

// ---------------- device scratch (zero-initialized statics) ----------------
__device__ __align__(256) float g_offs[(size_t)B * OSTR];
__device__ __align__(256) float g_fw  [(size_t)B * FSTR];
__device__ __align__(256) float g_fh  [(size_t)B * FSTR];
__device__ float g_avg [B * CMID];
__device__ float g_attn[B * 2];
__device__ float g_biasRO[576];
__device__ __align__(256) __half g_xp  [(size_t)B * 192 * HW];
__device__ __align__(256) __half g_xrp [(size_t)B * FSTR];
__device__ __align__(256) uint4  g_xrd [(size_t)B * G * 5 * XDE];
__device__ __align__(256) __half g_cw  [(size_t)B * CSTR];
__device__ __align__(256) __half g_ch  [(size_t)B * CSTR];
// prepacked weights: [plane(hi,lo)][Kpad][Mpad] k-major
__device__ __align__(256) __half g_wpRO[2 * 192 * 576];   // merged reduce+offset
__device__ __align__(256) __half g_wpW [2 * 1664 * 192];
__device__ __align__(256) __half g_wpH [2 * 1664 * 192];
__device__ __align__(256) __half g_wpE [2 * 192  * 192];

// ---------------- PTX helpers (arch-generic) ----------------
__device__ __forceinline__ uint32_t smem_to_u32(const void* p) {
    uint32_t a;
    asm("{ .reg .u64 t; cvta.to.shared.u64 t, %1; cvt.u32.u64 %0, t; }"
        : "=r"(a) : "l"(p));
    return a;
}
__device__ __forceinline__ void cp16(uint32_t dst, const void* src) {
    asm volatile("cp.async.cg.shared.global [%0], [%1], 16;" :: "r"(dst), "l"(src));
}
#define CP_COMMIT() asm volatile("cp.async.commit_group;" ::: "memory")
#define CP_WAIT(n)  asm volatile("cp.async.wait_group %0;" :: "n"(n) : "memory")

__device__ __forceinline__ void ldsm_x4_t(uint32_t* r, uint32_t addr) {
    asm volatile("ldmatrix.sync.aligned.m8n8.x4.trans.shared.b16 {%0,%1,%2,%3}, [%4];"
        : "=r"(r[0]), "=r"(r[1]), "=r"(r[2]), "=r"(r[3]) : "r"(addr));
}
__device__ __forceinline__ void mma16816(float* d, const uint32_t* a, const uint32_t* b) {
    asm volatile("mma.sync.aligned.m16n8k16.row.col.f32.f16.f16.f32 "
        "{%0,%1,%2,%3}, {%4,%5,%6,%7}, {%8,%9}, {%0,%1,%2,%3};"
        : "+f"(d[0]), "+f"(d[1]), "+f"(d[2]), "+f"(d[3])
        : "r"(a[0]), "r"(a[1]), "r"(a[2]), "r"(a[3]), "r"(b[0]), "r"(b[1]));
}

// ---------------- tensor GEMM: BK=64, 3-stage pipeline, 1 sync/chunk --------
// C[z][m][p] = sum_k W[m][k] * Act[z][k][p] + bias[m]
// RO: merged reduce(rows<192, 2-pass, fp16-plane out)+offset(rows>=192, 1-pass, f32 out)
template <int PASSES, bool WF, bool PLANES, bool MIX, bool DUAL, bool RO>
__global__ void __launch_bounds__(256, 1)
tgemm_kernel(const __half* __restrict__ actA, size_t strideAct,
             const float* __restrict__ mA, const float* __restrict__ mB,
             const float* __restrict__ attnp,
             const __half* __restrict__ WpA, int nChunks,
             const float* __restrict__ bias, int Mvalid,
             float* __restrict__ outFA, size_t strideOF,
             __half* __restrict__ outP, size_t strideOP,
             const __half* __restrict__ actB, const __half* __restrict__ WpB,
             const float* __restrict__ biasB, float* __restrict__ outFB)
{
    constexpr int NPL   = (PASSES == 2) ? 2 : 1;
    constexpr int A_BUF = NPL * 25600;
    constexpr int SMB_B = 3 * A_BUF;
    extern __shared__ char smem[];
    const uint32_t sb = smem_to_u32(smem);
    const int tid = threadIdx.x, lane = tid & 31, wid = tid >> 5;
    const int wm = wid & 3, wn = wid >> 2;
    const int zc = blockIdx.z;
    const int z    = DUAL ? (zc & 1) : zc;
    const int conv = DUAL ? (zc >> 1) : 0;
    const int yb = blockIdx.y;
    const int pbase = blockIdx.x * 128;
    const int Mpad = gridDim.y * 192;
    const size_t wPlane = (size_t)nChunks * 64 * Mpad;
    const bool twoPass = RO ? (yb == 0) : (PASSES == 2);

    const __half* Wp = (DUAL && conv) ? WpB : WpA;
    const float* biasp = (DUAL && conv) ? biasB : bias;
    const __half* actsel = (DUAL && conv) ? actB : actA;

    const __half* actz = MIX ? nullptr : (actsel + (size_t)z * strideAct + pbase);
    const float* mAz = MIX ? (mA + (size_t)z * strideAct + pbase) : nullptr;
    const float* mBz = MIX ? (mB + (size_t)z * strideAct + pbase) : nullptr;
    float c0 = 0.f, c1 = 0.f;
    if (MIX) { c0 = attnp[z * 2]; c1 = attnp[z * 2 + 1]; }

    auto loadChunk = [&](int kc, int s) {
#pragma unroll
        for (int i = 0; i < 6 * NPL; i++) {
            int c = tid + i * 256;
            int pl = c / 1536, rem = c % 1536, row = rem / 24, cc = rem % 24;
            if (pl == 0 || twoPass) {
                uint32_t dst = sb + s * A_BUF + pl * 25600 + row * 400 + cc * 16;
                const __half* src = Wp + (size_t)pl * wPlane
                    + (size_t)(kc * 64 + row) * Mpad + yb * 192 + cc * 8;
                cp16(dst, src);
            }
        }
#pragma unroll
        for (int i = 0; i < 4; i++) {
            int c = tid + i * 256;
            int row = c >> 4, cc = c & 15;
            uint32_t dst = sb + SMB_B + s * 17408 + row * 272 + cc * 16;
            if (!MIX) {
                cp16(dst, actz + (size_t)(kc * 64 + row) * HW + cc * 8);
            } else {
                size_t off = (size_t)(kc * 64 + row) * HW + cc * 8;
                float4 a0 = *reinterpret_cast<const float4*>(mAz + off);
                float4 a1 = *reinterpret_cast<const float4*>(mAz + off + 4);
                float4 b0 = *reinterpret_cast<const float4*>(mBz + off);
                float4 b1 = *reinterpret_cast<const float4*>(mBz + off + 4);
                __half2 h0 = __floats2half2_rn(c0 * a0.x + c1 * b0.x, c0 * a0.y + c1 * b0.y);
                __half2 h1 = __floats2half2_rn(c0 * a0.z + c1 * b0.z, c0 * a0.w + c1 * b0.w);
                __half2 h2 = __floats2half2_rn(c0 * a1.x + c1 * b1.x, c0 * a1.y + c1 * b1.y);
                __half2 h3 = __floats2half2_rn(c0 * a1.z + c1 * b1.z, c0 * a1.w + c1 * b1.w);
                asm volatile("st.shared.v4.b32 [%0], {%1, %2, %3, %4};"
                    :: "r"(dst),
                       "r"(*reinterpret_cast<uint32_t*>(&h0)),
                       "r"(*reinterpret_cast<uint32_t*>(&h1)),
                       "r"(*reinterpret_cast<uint32_t*>(&h2)),
                       "r"(*reinterpret_cast<uint32_t*>(&h3)) : "memory");
            }
        }
    };

    const uint32_t aRow  = ((lane >> 4) & 1) * 8 + (lane & 7);
    const uint32_t aColB = (uint32_t)(wm * 48 + ((lane >> 3) & 1) * 8) * 2;
    const uint32_t bRow  = ((lane >> 3) & 1) * 8 + (lane & 7);
    const uint32_t bColB = (uint32_t)(wn * 64 + ((lane >> 4) & 1) * 8) * 2;
    const uint32_t aAddr = sb + aRow * 400 + aColB;
    const uint32_t bAddr = sb + SMB_B + bRow * 272 + bColB;

    float acc[3][8][4];
#pragma unroll
    for (int i = 0; i < 3; i++)
#pragma unroll
        for (int j = 0; j < 8; j++)
#pragma unroll
            for (int q = 0; q < 4; q++) acc[i][j][q] = 0.f;

    loadChunk(0, 0);
    CP_COMMIT();
    if (nChunks > 1) { loadChunk(1, 1); CP_COMMIT(); }

    int s = 0;
    for (int t = 0; t < nChunks; t++) {
        if (t + 1 < nChunks) { CP_WAIT(1); } else { CP_WAIT(0); }
        __syncthreads();
        if (t + 2 < nChunks) {
            loadChunk(t + 2, (s + 2 >= 3) ? s - 1 : s + 2);
            CP_COMMIT();
        }

        const uint32_t aB = s * A_BUF, bB = s * 17408;
#pragma unroll
        for (int ks = 0; ks < 4; ks++) {
            uint32_t Ah[3][4], Al[3][4], Bf[4][4];
#pragma unroll
            for (int mt = 0; mt < 3; mt++) {
                ldsm_x4_t(Ah[mt], aAddr + aB + mt * 32 + ks * 6400);
                if (NPL == 2 && twoPass)
                    ldsm_x4_t(Al[mt], aAddr + aB + 25600 + mt * 32 + ks * 6400);
            }
#pragma unroll
            for (int ntp = 0; ntp < 4; ntp++)
                ldsm_x4_t(Bf[ntp], bAddr + bB + ntp * 32 + ks * 4352);
#pragma unroll
            for (int mt = 0; mt < 3; mt++)
#pragma unroll
                for (int nt = 0; nt < 8; nt++) {
                    const uint32_t* bp = &Bf[nt >> 1][(nt & 1) * 2];
                    mma16816(acc[mt][nt], Ah[mt], bp);
                    if (NPL == 2 && twoPass)
                        mma16816(acc[mt][nt], Al[mt], bp);
                }
        }
        if (++s == 3) s = 0;
    }

    // ---------------- epilogue ----------------
    if (RO) {
        __half* oPr = outP + (size_t)z * strideOP;
        float*  oFr = outFA + (size_t)z * strideOF;
#pragma unroll
        for (int mt = 0; mt < 3; mt++) {
#pragma unroll
            for (int half = 0; half < 2; half++) {
                const int m = yb * 192 + wm * 48 + mt * 16 + half * 8 + (lane >> 2);
                const float bv = bias[m];
#pragma unroll
                for (int nt = 0; nt < 8; nt++) {
                    const int n0 = pbase + wn * 64 + nt * 8 + (lane & 3) * 2;
                    float v0 = acc[mt][nt][half * 2 + 0] + bv;
                    float v1 = acc[mt][nt][half * 2 + 1] + bv;
                    if (yb == 0) {
                        if (m < 180)
                            *reinterpret_cast<__half2*>(&oPr[(size_t)m * HW + n0]) =
                                __floats2half2_rn(v0, v1);
                    } else {
                        int mo = m - 192;
                        if (mo < 360)
                            *reinterpret_cast<float2*>(&oFr[(size_t)mo * HW + n0]) =
                                make_float2(v0, v1);
                    }
                }
            }
        }
        return;
    }

    float* outF = (DUAL && conv) ? outFB : outFA;
    float* oF = WF ? (outF + (size_t)z * strideOF) : nullptr;
    __half* oP = PLANES ? (outP + (size_t)z * strideOP) : nullptr;
#pragma unroll
    for (int mt = 0; mt < 3; mt++) {
#pragma unroll
        for (int half = 0; half < 2; half++) {
            const int m = yb * 192 + wm * 48 + mt * 16 + half * 8 + (lane >> 2);
            if (m < Mvalid) {
                const float bv = biasp[m];
#pragma unroll
                for (int nt = 0; nt < 8; nt++) {
                    const int n0 = pbase + wn * 64 + nt * 8 + (lane & 3) * 2;
                    float v0 = acc[mt][nt][half * 2 + 0] + bv;
                    float v1 = acc[mt][nt][half * 2 + 1] + bv;
                    if (WF)
                        *reinterpret_cast<float2*>(&oF[(size_t)m * HW + n0]) =
                            make_float2(v0, v1);
                    if (PLANES)
                        *reinterpret_cast<__half2*>(&oP[(size_t)m * HW + n0]) =
                            __floats2half2_rn(v0, v1);
                }
            }
        }
    }
}

// ---------------- fused prep ----------------
__device__ __forceinline__ void wsplit(float v, __half* dst, size_t planeOff, int idx) {
    __half h = __float2half_rn(v);
    __half l = __float2half_rn(v - __half2float(h));
    dst[idx] = h;
    dst[planeOff + idx] = l;
}
__device__ __forceinline__ void prep_one(const float* W, int Kd, int Mvalid,
                                         int Mpad, int Kpad, __half* dst, int idx)
{
    int k = idx / Mpad, m = idx % Mpad;
    float v = (k < Kd && m < Mvalid) ? W[(size_t)m * Kd + k] : 0.f;
    wsplit(v, dst, (size_t)Kpad * Mpad, idx);
}

constexpr int N_RO = 192 * 576;
constexpr int N_BB = 576;
constexpr int N_W  = 1664 * 192;
constexpr int N_E  = 192 * 192;
constexpr int N_X  = (B * CIN * HW) / 2;
constexpr int PREP_TOTAL = N_RO + N_BB + 2 * N_W + N_E + N_X;

__global__ void prep_kernel(const float* __restrict__ w_reduce,
                            const float* __restrict__ b_reduce,
                            const float* __restrict__ w_offset,
                            const float* __restrict__ b_offset,
                            const float* __restrict__ w_dcnw,
                            const float* __restrict__ w_dcnh,
                            const float* __restrict__ w_expand,
                            const float* __restrict__ x,
                            __half* __restrict__ wpRO, float* __restrict__ biasRO,
                            __half* __restrict__ wpW, __half* __restrict__ wpH,
                            __half* __restrict__ wpE, __half* __restrict__ xp)
{
    int idx = blockIdx.x * blockDim.x + threadIdx.x;
    if (idx >= PREP_TOTAL) return;
    if (idx < N_RO) {
        // merged weight: rows [0,192)=reduce, [192,576)=W_offset@W_reduce
        int k = idx / 576, m = idx % 576;
        float v = 0.f;
        if (m < 192) {
            if (m < 180) v = w_reduce[(size_t)m * 192 + k];
        } else {
            int o = m - 192;
            if (o < 360) {
                const float* wo = w_offset + (size_t)o * 180;
                float acc = 0.f;
                for (int c = 0; c < 180; c += 2) {
                    float2 w2 = *reinterpret_cast<const float2*>(wo + c);
                    acc += w2.x * w_reduce[(size_t)c * 192 + k]
                         + w2.y * w_reduce[(size_t)(c + 1) * 192 + k];
                }
                v = acc;
            }
        }
        wsplit(v, wpRO, (size_t)N_RO, idx);
        return;
    }
    idx -= N_RO;
    if (idx < N_BB) {
        int m = idx;
        float v = 0.f;
        if (m < 180) v = b_reduce[m];
        else if (m >= 192 && m < 552) {
            int o = m - 192;
            float acc = b_offset[o];
            for (int c = 0; c < 180; c++)
                acc += w_offset[(size_t)o * 180 + c] * b_reduce[c];
            v = acc;
        }
        biasRO[m] = v;
        return;
    }
    idx -= N_BB;
    if (idx < N_W) { prep_one(w_dcnw, 1620, 180, 192, 1664, wpW, idx); return; }
    idx -= N_W;
    if (idx < N_W) { prep_one(w_dcnh, 1620, 180, 192, 1664, wpH, idx); return; }
    idx -= N_W;
    if (idx < N_E) { prep_one(w_expand, 180, 192, 192, 192, wpE, idx); return; }
    idx -= N_E;
    float2 v = reinterpret_cast<const float2*>(x)[idx];
    reinterpret_cast<__half2*>(xp)[idx] = __floats2half2_rn(v.x, v.y);
}

// ---------------- pack xrd: [b][g][q][entry] = 4ch x {p, p+1} fp16 ----------
__global__ void pack_xrd_kernel(const __half* __restrict__ xrp,
                                uint4* __restrict__ xrd)
{
    int idx = blockIdx.x * blockDim.x + threadIdx.x;
    int total = B * G * 5 * XDE;
    if (idx >= total) return;
    int e = idx % XDE;
    int rem = idx / XDE;
    int q = rem % 5;
    int gg = (rem / 5) % G;
    int b = rem / (5 * G);

    int p = e - 1;
    int pA = min(max(p, 0), HW - 1);
    int pB = min(p + 1, HW - 1);
    const __half* src = xrp + (size_t)b * FSTR;

    __half h[8];
#pragma unroll
    for (int j = 0; j < 4; j++) {
        int cl = 4 * q + j;
        if (cl < 18) {
            int c = gg * CG + cl;
            h[j]     = src[(size_t)c * HW + pA];
            h[4 + j] = src[(size_t)c * HW + pB];
        } else {
            h[j] = __ushort_as_half(0);
            h[4 + j] = __ushort_as_half(0);
        }
    }
    xrd[idx] = *reinterpret_cast<uint4*>(h);
}

// ---------------- deformable im2col v5: duplicated-pixel uint4 gathers ------
__global__ void __launch_bounds__(256)
im2col_kernel(const uint4* __restrict__ xrd, const float* __restrict__ offs,
              __half* __restrict__ cw, __half* __restrict__ chh)
{
    const int b = blockIdx.z, g = blockIdx.y;
    const int pp = blockIdx.x * 256 + threadIdx.x;
    const int p0 = pp * 2;
    const int h0 = p0 / Ww, w0 = p0 % Ww;

    const uint4* xd = xrd + ((size_t)(b * G + g) * 5) * XDE + 1;

    for (int conv = 0; conv < 2; conv++) {
        const float* offb = offs + (size_t)b * OSTR
            + (size_t)((conv ? CMID : 0) + g * 18) * HW;
        __half* colb = (conv ? chh : cw) + (size_t)b * CSTR
            + (size_t)(g * CG) * KK * HW + p0;

        for (int kk = 0; kk < KK; kk++) {
            float2 oy = *reinterpret_cast<const float2*>(&offb[(size_t)(kk * 2) * HW + p0]);
            float2 ox = *reinterpret_cast<const float2*>(&offb[(size_t)(kk * 2 + 1) * HW + p0]);

            float a0[20], a1[20];
#pragma unroll
            for (int c = 0; c < 20; c++) { a0[c] = 0.f; a1[c] = 0.f; }

#pragma unroll
            for (int px = 0; px < 2; px++) {
                float sy = (px ? oy.y : oy.x) + (float)(kk / 3 - 1 + h0);
                float sx = (px ? ox.y : ox.x) + (float)(kk % 3 - 1 + w0 + px);
                float y0f = floorf(sy), x0f = floorf(sx);
                float dy = sy - y0f, dx = sx - x0f;
                int y0 = (int)y0f, x0 = (int)x0f;
                int y1 = y0 + 1, x1 = x0 + 1;
                bool vy0 = (y0 >= 0) & (y0 < Hh);
                bool vy1 = (y1 >= 0) & (y1 < Hh);
                bool vx0 = (x0 >= 0) & (x0 < Ww);
                bool vx1 = (x1 >= 0) & (x1 < Ww);
                int y0c = min(max(y0, 0), Hh - 1);
                int y1c = min(max(y1, 0), Hh - 1);
                int x0c = min(max(x0, 0), Ww - 1);
                int x1c = min(max(x1, 0), Ww - 1);
                int basex = vx1 ? (x1c - 1) : x0c;
                float w00 = (1.f - dy) * (1.f - dx) * (float)(vy0 && vx0);
                float w01 = (1.f - dy) * dx        * (float)(vy0 && vx1);
                float w10 = dy * (1.f - dx)        * (float)(vy1 && vx0);
                float w11 = dy * dx                * (float)(vy1 && vx1);
                int e0 = y0c * Ww + basex;
                int e1 = y1c * Ww + basex;
                float* acc = px ? a1 : a0;

#pragma unroll
                for (int r = 0; r < 2; r++) {
                    const float ws0 = r ? w10 : w00;
                    const float ws1 = r ? w11 : w01;
                    const int base = r ? e1 : e0;
#pragma unroll
                    for (int q = 0; q < 5; q++) {
                        uint4 v = xd[(size_t)q * XDE + base];
                        float2 fA0 = __half22float2(*reinterpret_cast<__half2*>(&v.x));
                        float2 fA1 = __half22float2(*reinterpret_cast<__half2*>(&v.y));
                        float2 fB0 = __half22float2(*reinterpret_cast<__half2*>(&v.z));
                        float2 fB1 = __half22float2(*reinterpret_cast<__half2*>(&v.w));
                        acc[4 * q + 0] += ws0 * fA0.x + ws1 * fB0.x;
                        acc[4 * q + 1] += ws0 * fA0.y + ws1 * fB0.y;
                        acc[4 * q + 2] += ws0 * fA1.x + ws1 * fB1.x;
                        acc[4 * q + 3] += ws0 * fA1.y + ws1 * fB1.y;
                    }
                }
            }
#pragma unroll
            for (int c = 0; c < 18; c++)
                *reinterpret_cast<__half2*>(&colb[(size_t)(c * KK + kk) * HW]) =
                    __floats2half2_rn(a0[c], a1[c]);
        }
    }
}

// ---------------- mean over HW of (fw+fh) per (b,c) ----------------
__global__ void reduce_mean_kernel(const float* __restrict__ fw,
                                   const float* __restrict__ fh,
                                   float* __restrict__ avg)
{
    const int bc = blockIdx.x;
    const int bb = bc / CMID, cc = bc % CMID;
    const float* a = fw + (size_t)bb * FSTR + (size_t)cc * HW;
    const float* b = fh + (size_t)bb * FSTR + (size_t)cc * HW;
    float s = 0.f;
    for (int i = threadIdx.x; i < HW; i += 256) s += a[i] + b[i];
    __shared__ float sm[256];
    sm[threadIdx.x] = s;
    __syncthreads();
    for (int st = 128; st > 0; st >>= 1) {
        if (threadIdx.x < st) sm[threadIdx.x] += sm[threadIdx.x + st];
        __syncthreads();
    }
    if (threadIdx.x == 0) avg[bc] = sm[0] * (1.0f / HW);
}

// ---------------- attention softmax ----------------
__global__ void attn_kernel(const float* __restrict__ avg,
                            const float* __restrict__ w_attn,
                            const float* __restrict__ b_attn,
                            float* __restrict__ attn)
{
    const int t = threadIdx.x;
    __shared__ float logits[4];
    if (t < 4) {
        int b = t >> 1, o = t & 1;
        float s = b_attn[o];
        for (int c = 0; c < CMID; c++)
            s += avg[b * CMID + c] * w_attn[o * CMID + c];
        logits[t] = s;
    }
    __syncthreads();
    if (t < 2) {
        float l0 = logits[t * 2 + 0], l1 = logits[t * 2 + 1];
        float m = fmaxf(l0, l1);
        float e0 = expf(l0 - m), e1 = expf(l1 - m);
        float inv = 1.f / (e0 + e1);
        attn[t * 2 + 0] = e0 * inv;   // f_h weight
        attn[t * 2 + 1] = e1 * inv;   // f_w weight
    }
}

// ---------------- launcher ----------------
extern "C" void kernel_launch(void* const* d_in, const int* in_sizes, int n_in,
                              void* d_out, int out_size)
{
    const float* x        = (const float*)d_in[0];
    const float* w_reduce = (const float*)d_in[1];
    const float* b_reduce = (const float*)d_in[2];
    const float* w_offset = (const float*)d_in[3];
    const float* b_offset = (const float*)d_in[4];
    const float* w_dcnw   = (const float*)d_in[5];
    const float* b_dcnw   = (const float*)d_in[6];
    const float* w_dcnh   = (const float*)d_in[7];
    const float* b_dcnh   = (const float*)d_in[8];
    const float* w_expand = (const float*)d_in[9];
    const float* b_expand = (const float*)d_in[10];
    const float* w_attn   = (const float*)d_in[11];
    const float* b_attn   = (const float*)d_in[12];
    float* out = (float*)d_out;

    float *offs, *fw, *fh, *avg, *attn, *biasRO;
    cudaGetSymbolAddress((void**)&offs, g_offs);
    cudaGetSymbolAddress((void**)&fw,   g_fw);
    cudaGetSymbolAddress((void**)&fh,   g_fh);
    cudaGetSymbolAddress((void**)&avg,  g_avg);
    cudaGetSymbolAddress((void**)&attn, g_attn);
    cudaGetSymbolAddress((void**)&biasRO, g_biasRO);
    __half *xp, *xrp, *cw, *ch, *wpRO, *wpW, *wpH, *wpE;
    uint4* xrd;
    cudaGetSymbolAddress((void**)&xp,   g_xp);
    cudaGetSymbolAddress((void**)&xrp,  g_xrp);
    cudaGetSymbolAddress((void**)&xrd,  g_xrd);
    cudaGetSymbolAddress((void**)&cw,   g_cw);
    cudaGetSymbolAddress((void**)&ch,   g_ch);
    cudaGetSymbolAddress((void**)&wpRO, g_wpRO);
    cudaGetSymbolAddress((void**)&wpW,  g_wpW);
    cudaGetSymbolAddress((void**)&wpH,  g_wpH);
    cudaGetSymbolAddress((void**)&wpE,  g_wpE);

    constexpr int SM2 = 3 * 2 * 25600 + 3 * 17408;   // 205824
    constexpr int SM1 = 3 * 1 * 25600 + 3 * 17408;   // 129024
    cudaFuncSetAttribute((const void*)tgemm_kernel<2, false, false, false, false, true>,
                         cudaFuncAttributeMaxDynamicSharedMemorySize, SM2);
    cudaFuncSetAttribute((const void*)tgemm_kernel<1, true,  false, false, true,  false>,
                         cudaFuncAttributeMaxDynamicSharedMemorySize, SM1);
    cudaFuncSetAttribute((const void*)tgemm_kernel<1, true,  false, true,  false, false>,
                         cudaFuncAttributeMaxDynamicSharedMemorySize, SM1);

    // 1) prep: merged RO weight+bias, deform/expand prepacks, x->fp16
    prep_kernel<<<(PREP_TOTAL + 255) / 256, 256>>>(
        w_reduce, b_reduce, w_offset, b_offset, w_dcnw, w_dcnh, w_expand, x,
        wpRO, biasRO, wpW, wpH, wpE, xp);

    // 2) merged reduce+offset GEMM: M=576 (rows<192: xr fp16 plane, 2-pass;
    //    rows>=192: offs f32, 1-pass), K=192 (3 chunks), input xp
    tgemm_kernel<2, false, false, false, false, true><<<dim3(72, 3, B), 256, SM2>>>(
        xp, (size_t)192 * HW, nullptr, nullptr, nullptr,
        wpRO, 3, biasRO, 0, offs, OSTR, xrp, FSTR,
        nullptr, nullptr, nullptr, nullptr);

    // 3) pack duplicated-pixel gather tensor
    pack_xrd_kernel<<<(B * G * 5 * XDE + 255) / 256, 256>>>(xrp, xrd);

    // 4) im2col -> fp16 col planes (both convs)
    im2col_kernel<<<dim3(HW / 512, G, B), 256>>>(xrd, offs, cw, ch);

    // 5) BOTH deform GEMMs in one launch: 1-pass (26 chunks), f32 out
    tgemm_kernel<1, true, false, false, true, false><<<dim3(72, 1, 2 * B), 256, SM1>>>(
        cw, CSTR, nullptr, nullptr, nullptr,
        wpW, 26, b_dcnw, 180, fw, FSTR, nullptr, 0,
        ch, wpH, b_dcnh, fh);

    // 6) attention
    reduce_mean_kernel<<<B * CMID, 256>>>(fw, fh, avg);
    attn_kernel<<<1, 64>>>(avg, w_attn, b_attn, attn);

    // 7) out = expand(attn0*f_h + attn1*f_w): 1-pass (3 chunks), mix fused
    tgemm_kernel<1, true, false, true, false, false><<<dim3(72, 1, B), 256, SM1>>>(
        nullptr, FSTR, fh, fw, attn,
        wpE, 3, b_expand, 192, out, (size_t)CIN * HW, nullptr, 0,
        nullptr, nullptr, nullptr, nullptr);
}

// round 16
// speedup vs baseline: 1.0565x; 1.0565x over previous
#include <cuda_runtime.h>
#include <cuda_fp16.h>
#include <math.h>
#include <stdint.h>

// ---------------- problem constants ----------------
constexpr int B    = 2;
constexpr int CIN  = 192;
constexpr int CMID = 180;
constexpr int Hh   = 96;
constexpr int Ww   = 96;
constexpr int HW   = Hh * Ww;          // 9216
constexpr int KK   = 9;
constexpr int G    = 10;
constexpr int CG   = CMID / G;         // 18
constexpr int KDIM_P = 1664;           // 26 chunks of 64

constexpr size_t FSTR = (size_t)192 * HW;      // feature stride (pad rows zero)
constexpr size_t OSTR = (size_t)360 * HW;      // offs stride
constexpr size_t CSTR = (size_t)KDIM_P * HW;   // col plane stride
constexpr int    XDE  = HW + 2;                // xrd entries per quad (+pad)

// ---------------- device scratch (zero-initialized statics) ----------------
__device__ __align__(256) float g_offs[(size_t)B * OSTR];
__device__ __align__(256) float g_fw  [(size_t)B * FSTR];
__device__ __align__(256) float g_fh  [(size_t)B * FSTR];
__device__ float g_avg [B * CMID];
__device__ float g_attn[B * 2];
__device__ __align__(256) __half g_xp  [(size_t)B * 192 * HW];
__device__ __align__(256) __half g_xrp [(size_t)B * FSTR];
__device__ __align__(256) uint4  g_xrd [(size_t)B * G * 5 * XDE];
__device__ __align__(256) __half g_cw  [(size_t)B * CSTR];
__device__ __align__(256) __half g_ch  [(size_t)B * CSTR];
// prepacked weights: [plane(hi,lo)][Kpad][Mpad] k-major
__device__ __align__(256) __half g_wpR[2 * 192  * 192];
__device__ __align__(256) __half g_wpO[2 * 192  * 384];
__device__ __align__(256) __half g_wpW[2 * 1664 * 192];
__device__ __align__(256) __half g_wpH[2 * 1664 * 192];
__device__ __align__(256) __half g_wpE[2 * 192  * 192];

// ---------------- PTX helpers (arch-generic) ----------------
__device__ __forceinline__ uint32_t smem_to_u32(const void* p) {
    uint32_t a;
    asm("{ .reg .u64 t; cvta.to.shared.u64 t, %1; cvt.u32.u64 %0, t; }"
        : "=r"(a) : "l"(p));
    return a;
}
__device__ __forceinline__ void cp16(uint32_t dst, const void* src) {
    asm volatile("cp.async.cg.shared.global [%0], [%1], 16;" :: "r"(dst), "l"(src));
}
#define CP_COMMIT() asm volatile("cp.async.commit_group;" ::: "memory")
#define CP_WAIT(n)  asm volatile("cp.async.wait_group %0;" :: "n"(n) : "memory")

__device__ __forceinline__ void ldsm_x4_t(uint32_t* r, uint32_t addr) {
    asm volatile("ldmatrix.sync.aligned.m8n8.x4.trans.shared.b16 {%0,%1,%2,%3}, [%4];"
        : "=r"(r[0]), "=r"(r[1]), "=r"(r[2]), "=r"(r[3]) : "r"(addr));
}
__device__ __forceinline__ void mma16816(float* d, const uint32_t* a, const uint32_t* b) {
    asm volatile("mma.sync.aligned.m16n8k16.row.col.f32.f16.f16.f32 "
        "{%0,%1,%2,%3}, {%4,%5,%6,%7}, {%8,%9}, {%0,%1,%2,%3};"
        : "+f"(d[0]), "+f"(d[1]), "+f"(d[2]), "+f"(d[3])
        : "r"(a[0]), "r"(a[1]), "r"(a[2]), "r"(a[3]), "r"(b[0]), "r"(b[1]));
}

// ---------------- tensor GEMM: BK=64, 3-stage pipeline, 1 sync/chunk --------
// C[z][m][p] = sum_k W[m][k] * Act[z][k][p] + bias[m]
// grid = (72, Mpad/192, B or 2B when DUAL). 8 warps: 4m x 2n (48x64 tiles).
template <int PASSES, bool WF, bool PLANES, bool MIX, bool DUAL>
__global__ void __launch_bounds__(256, 1)
tgemm_kernel(const __half* __restrict__ actA, size_t strideAct,
             const float* __restrict__ mA, const float* __restrict__ mB,
             const float* __restrict__ attnp,
             const __half* __restrict__ WpA, int nChunks,
             const float* __restrict__ biasA, int Mvalid,
             float* __restrict__ outFA, size_t strideOF,
             __half* __restrict__ outP, size_t strideOP,
             const __half* __restrict__ actB, const __half* __restrict__ WpB,
             const float* __restrict__ biasB, float* __restrict__ outFB)
{
    constexpr int A_BUF = PASSES * 25600;       // per-stage A bytes
    constexpr int SMB_B = 3 * A_BUF;            // B region base
    extern __shared__ char smem[];
    const uint32_t sb = smem_to_u32(smem);
    const int tid = threadIdx.x, lane = tid & 31, wid = tid >> 5;
    const int wm = wid & 3, wn = wid >> 2;
    const int zc = blockIdx.z;
    const int z    = DUAL ? (zc & 1) : zc;
    const int conv = DUAL ? (zc >> 1) : 0;
    const int yb = blockIdx.y;
    const int pbase = blockIdx.x * 128;
    const int Mpad = gridDim.y * 192;
    const size_t wPlane = (size_t)nChunks * 64 * Mpad;

    const __half* Wp = (DUAL && conv) ? WpB : WpA;
    const float* bias = (DUAL && conv) ? biasB : biasA;
    const __half* actsel = (DUAL && conv) ? actB : actA;

    const __half* actz = MIX ? nullptr : (actsel + (size_t)z * strideAct + pbase);
    const float* mAz = MIX ? (mA + (size_t)z * strideAct + pbase) : nullptr;
    const float* mBz = MIX ? (mB + (size_t)z * strideAct + pbase) : nullptr;
    float c0 = 0.f, c1 = 0.f;
    if (MIX) { c0 = attnp[z * 2]; c1 = attnp[z * 2 + 1]; }

    auto loadChunk = [&](int kc, int s) {
#pragma unroll
        for (int i = 0; i < 6 * PASSES; i++) {
            int c = tid + i * 256;
            int pl = c / 1536, rem = c % 1536, row = rem / 24, cc = rem % 24;
            uint32_t dst = sb + s * A_BUF + pl * 25600 + row * 400 + cc * 16;
            const __half* src = Wp + (size_t)pl * wPlane
                + (size_t)(kc * 64 + row) * Mpad + yb * 192 + cc * 8;
            cp16(dst, src);
        }
#pragma unroll
        for (int i = 0; i < 4; i++) {
            int c = tid + i * 256;
            int row = c >> 4, cc = c & 15;
            uint32_t dst = sb + SMB_B + s * 17408 + row * 272 + cc * 16;
            if (!MIX) {
                cp16(dst, actz + (size_t)(kc * 64 + row) * HW + cc * 8);
            } else {
                size_t off = (size_t)(kc * 64 + row) * HW + cc * 8;
                float4 a0 = *reinterpret_cast<const float4*>(mAz + off);
                float4 a1 = *reinterpret_cast<const float4*>(mAz + off + 4);
                float4 b0 = *reinterpret_cast<const float4*>(mBz + off);
                float4 b1 = *reinterpret_cast<const float4*>(mBz + off + 4);
                __half2 h0 = __floats2half2_rn(c0 * a0.x + c1 * b0.x, c0 * a0.y + c1 * b0.y);
                __half2 h1 = __floats2half2_rn(c0 * a0.z + c1 * b0.z, c0 * a0.w + c1 * b0.w);
                __half2 h2 = __floats2half2_rn(c0 * a1.x + c1 * b1.x, c0 * a1.y + c1 * b1.y);
                __half2 h3 = __floats2half2_rn(c0 * a1.z + c1 * b1.z, c0 * a1.w + c1 * b1.w);
                asm volatile("st.shared.v4.b32 [%0], {%1, %2, %3, %4};"
                    :: "r"(dst),
                       "r"(*reinterpret_cast<uint32_t*>(&h0)),
                       "r"(*reinterpret_cast<uint32_t*>(&h1)),
                       "r"(*reinterpret_cast<uint32_t*>(&h2)),
                       "r"(*reinterpret_cast<uint32_t*>(&h3)) : "memory");
            }
        }
    };

    const uint32_t aRow  = ((lane >> 4) & 1) * 8 + (lane & 7);
    const uint32_t aColB = (uint32_t)(wm * 48 + ((lane >> 3) & 1) * 8) * 2;
    const uint32_t bRow  = ((lane >> 3) & 1) * 8 + (lane & 7);
    const uint32_t bColB = (uint32_t)(wn * 64 + ((lane >> 4) & 1) * 8) * 2;
    const uint32_t aAddr = sb + aRow * 400 + aColB;
    const uint32_t bAddr = sb + SMB_B + bRow * 272 + bColB;

    float acc[3][8][4];
#pragma unroll
    for (int i = 0; i < 3; i++)
#pragma unroll
        for (int j = 0; j < 8; j++)
#pragma unroll
            for (int q = 0; q < 4; q++) acc[i][j][q] = 0.f;

    // prologue: stages 0 and 1
    loadChunk(0, 0);
    CP_COMMIT();
    if (nChunks > 1) { loadChunk(1, 1); CP_COMMIT(); }

    int s = 0;
    for (int t = 0; t < nChunks; t++) {
        if (t + 1 < nChunks) { CP_WAIT(1); } else { CP_WAIT(0); }
        __syncthreads();    // all warps done with stage (t+2)%3's old contents
        if (t + 2 < nChunks) {
            loadChunk(t + 2, (s + 2 >= 3) ? s - 1 : s + 2);
            CP_COMMIT();
        }

        const uint32_t aB = s * A_BUF, bB = s * 17408;
#pragma unroll
        for (int ks = 0; ks < 4; ks++) {
            uint32_t Ah[3][4], Al[3][4], Bf[4][4];
#pragma unroll
            for (int mt = 0; mt < 3; mt++) {
                ldsm_x4_t(Ah[mt], aAddr + aB + mt * 32 + ks * 6400);
                if (PASSES == 2)
                    ldsm_x4_t(Al[mt], aAddr + aB + 25600 + mt * 32 + ks * 6400);
            }
#pragma unroll
            for (int ntp = 0; ntp < 4; ntp++)
                ldsm_x4_t(Bf[ntp], bAddr + bB + ntp * 32 + ks * 4352);
#pragma unroll
            for (int mt = 0; mt < 3; mt++)
#pragma unroll
                for (int nt = 0; nt < 8; nt++) {
                    const uint32_t* bp = &Bf[nt >> 1][(nt & 1) * 2];
                    mma16816(acc[mt][nt], Ah[mt], bp);
                    if (PASSES == 2)
                        mma16816(acc[mt][nt], Al[mt], bp);
                }
        }
        if (++s == 3) s = 0;
    }

    float* outF = (DUAL && conv) ? outFB : outFA;
    float* oF = WF ? (outF + (size_t)z * strideOF) : nullptr;
    __half* oP = PLANES ? (outP + (size_t)z * strideOP) : nullptr;
#pragma unroll
    for (int mt = 0; mt < 3; mt++) {
#pragma unroll
        for (int half = 0; half < 2; half++) {
            const int m = yb * 192 + wm * 48 + mt * 16 + half * 8 + (lane >> 2);
            if (m < Mvalid) {
                const float bv = bias[m];
#pragma unroll
                for (int nt = 0; nt < 8; nt++) {
                    const int n0 = pbase + wn * 64 + nt * 8 + (lane & 3) * 2;
                    float v0 = acc[mt][nt][half * 2 + 0] + bv;
                    float v1 = acc[mt][nt][half * 2 + 1] + bv;
                    if (WF)
                        *reinterpret_cast<float2*>(&oF[(size_t)m * HW + n0]) =
                            make_float2(v0, v1);
                    if (PLANES)
                        *reinterpret_cast<__half2*>(&oP[(size_t)m * HW + n0]) =
                            __floats2half2_rn(v0, v1);
                }
            }
        }
    }
}

// ---------------- fused prep: weight prepacks + x->fp16 ----------------
__device__ __forceinline__ void prep_one(const float* W, int Kd, int Mvalid,
                                         int Mpad, int Kpad, __half* dst, int idx)
{
    int k = idx / Mpad, m = idx % Mpad;
    float v = (k < Kd && m < Mvalid) ? W[(size_t)m * Kd + k] : 0.f;
    __half h = __float2half_rn(v);
    __half l = __float2half_rn(v - __half2float(h));
    dst[idx] = h;
    dst[(size_t)Kpad * Mpad + idx] = l;
}

constexpr int N_R = 192 * 192;
constexpr int N_O = 192 * 384;
constexpr int N_W = 1664 * 192;
constexpr int N_E = 192 * 192;
constexpr int N_X = (B * CIN * HW) / 2;
constexpr int PREP_TOTAL = N_R + N_O + 2 * N_W + N_E + N_X;

__global__ void prep_kernel(const float* __restrict__ w_reduce,
                            const float* __restrict__ w_offset,
                            const float* __restrict__ w_dcnw,
                            const float* __restrict__ w_dcnh,
                            const float* __restrict__ w_expand,
                            const float* __restrict__ x,
                            __half* __restrict__ wpR, __half* __restrict__ wpO,
                            __half* __restrict__ wpW, __half* __restrict__ wpH,
                            __half* __restrict__ wpE, __half* __restrict__ xp)
{
    int idx = blockIdx.x * blockDim.x + threadIdx.x;
    if (idx >= PREP_TOTAL) return;
    if (idx < N_R) { prep_one(w_reduce, 192, 180, 192, 192, wpR, idx); return; }
    idx -= N_R;
    if (idx < N_O) { prep_one(w_offset, 180, 360, 384, 192, wpO, idx); return; }
    idx -= N_O;
    if (idx < N_W) { prep_one(w_dcnw, 1620, 180, 192, 1664, wpW, idx); return; }
    idx -= N_W;
    if (idx < N_W) { prep_one(w_dcnh, 1620, 180, 192, 1664, wpH, idx); return; }
    idx -= N_W;
    if (idx < N_E) { prep_one(w_expand, 180, 192, 192, 192, wpE, idx); return; }
    idx -= N_E;
    float2 v = reinterpret_cast<const float2*>(x)[idx];
    reinterpret_cast<__half2*>(xp)[idx] = __floats2half2_rn(v.x, v.y);
}

// ---------------- pack xrd: [b][g][q][entry] = 4ch x {p, p+1} fp16 ----------
__global__ void pack_xrd_kernel(const __half* __restrict__ xrp,
                                uint4* __restrict__ xrd)
{
    int idx = blockIdx.x * blockDim.x + threadIdx.x;
    int total = B * G * 5 * XDE;
    if (idx >= total) return;
    int e = idx % XDE;
    int rem = idx / XDE;
    int q = rem % 5;
    int gg = (rem / 5) % G;
    int b = rem / (5 * G);

    int p = e - 1;
    int pA = min(max(p, 0), HW - 1);
    int pB = min(p + 1, HW - 1);
    const __half* src = xrp + (size_t)b * FSTR;

    __half h[8];
#pragma unroll
    for (int j = 0; j < 4; j++) {
        int cl = 4 * q + j;
        if (cl < 18) {
            int c = gg * CG + cl;
            h[j]     = src[(size_t)c * HW + pA];
            h[4 + j] = src[(size_t)c * HW + pB];
        } else {
            h[j] = __ushort_as_half(0);
            h[4 + j] = __ushort_as_half(0);
        }
    }
    xrd[idx] = *reinterpret_cast<uint4*>(h);
}

// ---------------- deformable im2col v6: conv split across grid.z ------------
// grid = (HW/512, G, 2B); z = b + B*conv. 2 px/thread, duplicated-pixel gathers
__global__ void __launch_bounds__(256)
im2col_kernel(const uint4* __restrict__ xrd, const float* __restrict__ offs,
              __half* __restrict__ cw, __half* __restrict__ chh)
{
    const int b = blockIdx.z % B, conv = blockIdx.z / B;
    const int g = blockIdx.y;
    const int pp = blockIdx.x * 256 + threadIdx.x;
    const int p0 = pp * 2;
    const int h0 = p0 / Ww, w0 = p0 % Ww;

    const uint4* xd = xrd + ((size_t)(b * G + g) * 5) * XDE + 1;

    const float* offb = offs + (size_t)b * OSTR
        + (size_t)((conv ? CMID : 0) + g * 18) * HW;
    __half* colb = (conv ? chh : cw) + (size_t)b * CSTR
        + (size_t)(g * CG) * KK * HW + p0;

    for (int kk = 0; kk < KK; kk++) {
        float2 oy = *reinterpret_cast<const float2*>(&offb[(size_t)(kk * 2) * HW + p0]);
        float2 ox = *reinterpret_cast<const float2*>(&offb[(size_t)(kk * 2 + 1) * HW + p0]);

        float a0[20], a1[20];
#pragma unroll
        for (int c = 0; c < 20; c++) { a0[c] = 0.f; a1[c] = 0.f; }

#pragma unroll
        for (int px = 0; px < 2; px++) {
            float sy = (px ? oy.y : oy.x) + (float)(kk / 3 - 1 + h0);
            float sx = (px ? ox.y : ox.x) + (float)(kk % 3 - 1 + w0 + px);
            float y0f = floorf(sy), x0f = floorf(sx);
            float dy = sy - y0f, dx = sx - x0f;
            int y0 = (int)y0f, x0 = (int)x0f;
            int y1 = y0 + 1, x1 = x0 + 1;
            bool vy0 = (y0 >= 0) & (y0 < Hh);
            bool vy1 = (y1 >= 0) & (y1 < Hh);
            bool vx0 = (x0 >= 0) & (x0 < Ww);
            bool vx1 = (x1 >= 0) & (x1 < Ww);
            int y0c = min(max(y0, 0), Hh - 1);
            int y1c = min(max(y1, 0), Hh - 1);
            int x0c = min(max(x0, 0), Ww - 1);
            int x1c = min(max(x1, 0), Ww - 1);
            int basex = vx1 ? (x1c - 1) : x0c;
            float w00 = (1.f - dy) * (1.f - dx) * (float)(vy0 && vx0);
            float w01 = (1.f - dy) * dx        * (float)(vy0 && vx1);
            float w10 = dy * (1.f - dx)        * (float)(vy1 && vx0);
            float w11 = dy * dx                * (float)(vy1 && vx1);
            int e0 = y0c * Ww + basex;
            int e1 = y1c * Ww + basex;
            float* acc = px ? a1 : a0;

#pragma unroll
            for (int r = 0; r < 2; r++) {
                const float ws0 = r ? w10 : w00;
                const float ws1 = r ? w11 : w01;
                const int base = r ? e1 : e0;
#pragma unroll
                for (int q = 0; q < 5; q++) {
                    uint4 v = xd[(size_t)q * XDE + base];
                    float2 fA0 = __half22float2(*reinterpret_cast<__half2*>(&v.x));
                    float2 fA1 = __half22float2(*reinterpret_cast<__half2*>(&v.y));
                    float2 fB0 = __half22float2(*reinterpret_cast<__half2*>(&v.z));
                    float2 fB1 = __half22float2(*reinterpret_cast<__half2*>(&v.w));
                    acc[4 * q + 0] += ws0 * fA0.x + ws1 * fB0.x;
                    acc[4 * q + 1] += ws0 * fA0.y + ws1 * fB0.y;
                    acc[4 * q + 2] += ws0 * fA1.x + ws1 * fB1.x;
                    acc[4 * q + 3] += ws0 * fA1.y + ws1 * fB1.y;
                }
            }
        }
#pragma unroll
        for (int c = 0; c < 18; c++)
            *reinterpret_cast<__half2*>(&colb[(size_t)(c * KK + kk) * HW]) =
                __floats2half2_rn(a0[c], a1[c]);
    }
}

// ---------------- mean over HW of (fw+fh) per (b,c) ----------------
__global__ void reduce_mean_kernel(const float* __restrict__ fw,
                                   const float* __restrict__ fh,
                                   float* __restrict__ avg)
{
    const int bc = blockIdx.x;
    const int bb = bc / CMID, cc = bc % CMID;
    const float* a = fw + (size_t)bb * FSTR + (size_t)cc * HW;
    const float* b = fh + (size_t)bb * FSTR + (size_t)cc * HW;
    float s = 0.f;
    for (int i = threadIdx.x; i < HW; i += 256) s += a[i] + b[i];
    __shared__ float sm[256];
    sm[threadIdx.x] = s;
    __syncthreads();
    for (int st = 128; st > 0; st >>= 1) {
        if (threadIdx.x < st) sm[threadIdx.x] += sm[threadIdx.x + st];
        __syncthreads();
    }
    if (threadIdx.x == 0) avg[bc] = sm[0] * (1.0f / HW);
}

// ---------------- attention softmax ----------------
__global__ void attn_kernel(const float* __restrict__ avg,
                            const float* __restrict__ w_attn,
                            const float* __restrict__ b_attn,
                            float* __restrict__ attn)
{
    const int t = threadIdx.x;
    __shared__ float logits[4];
    if (t < 4) {
        int b = t >> 1, o = t & 1;
        float s = b_attn[o];
        for (int c = 0; c < CMID; c++)
            s += avg[b * CMID + c] * w_attn[o * CMID + c];
        logits[t] = s;
    }
    __syncthreads();
    if (t < 2) {
        float l0 = logits[t * 2 + 0], l1 = logits[t * 2 + 1];
        float m = fmaxf(l0, l1);
        float e0 = expf(l0 - m), e1 = expf(l1 - m);
        float inv = 1.f / (e0 + e1);
        attn[t * 2 + 0] = e0 * inv;   // f_h weight
        attn[t * 2 + 1] = e1 * inv;   // f_w weight
    }
}

// ---------------- launcher ----------------
extern "C" void kernel_launch(void* const* d_in, const int* in_sizes, int n_in,
                              void* d_out, int out_size)
{
    const float* x        = (const float*)d_in[0];
    const float* w_reduce = (const float*)d_in[1];
    const float* b_reduce = (const float*)d_in[2];
    const float* w_offset = (const float*)d_in[3];
    const float* b_offset = (const float*)d_in[4];
    const float* w_dcnw   = (const float*)d_in[5];
    const float* b_dcnw   = (const float*)d_in[6];
    const float* w_dcnh   = (const float*)d_in[7];
    const float* b_dcnh   = (const float*)d_in[8];
    const float* w_expand = (const float*)d_in[9];
    const float* b_expand = (const float*)d_in[10];
    const float* w_attn   = (const float*)d_in[11];
    const float* b_attn   = (const float*)d_in[12];
    float* out = (float*)d_out;

    float *offs, *fw, *fh, *avg, *attn;
    cudaGetSymbolAddress((void**)&offs, g_offs);
    cudaGetSymbolAddress((void**)&fw,   g_fw);
    cudaGetSymbolAddress((void**)&fh,   g_fh);
    cudaGetSymbolAddress((void**)&avg,  g_avg);
    cudaGetSymbolAddress((void**)&attn, g_attn);
    __half *xp, *xrp, *cw, *ch, *wpR, *wpO, *wpW, *wpH, *wpE;
    uint4* xrd;
    cudaGetSymbolAddress((void**)&xp,  g_xp);
    cudaGetSymbolAddress((void**)&xrp, g_xrp);
    cudaGetSymbolAddress((void**)&xrd, g_xrd);
    cudaGetSymbolAddress((void**)&cw,  g_cw);
    cudaGetSymbolAddress((void**)&ch,  g_ch);
    cudaGetSymbolAddress((void**)&wpR, g_wpR);
    cudaGetSymbolAddress((void**)&wpO, g_wpO);
    cudaGetSymbolAddress((void**)&wpW, g_wpW);
    cudaGetSymbolAddress((void**)&wpH, g_wpH);
    cudaGetSymbolAddress((void**)&wpE, g_wpE);

    constexpr int SM2 = 3 * 2 * 25600 + 3 * 17408;   // 205824
    constexpr int SM1 = 3 * 1 * 25600 + 3 * 17408;   // 129024
    cudaFuncSetAttribute((const void*)tgemm_kernel<2, false, true,  false, false>,
                         cudaFuncAttributeMaxDynamicSharedMemorySize, SM2);
    cudaFuncSetAttribute((const void*)tgemm_kernel<1, true,  false, false, false>,
                         cudaFuncAttributeMaxDynamicSharedMemorySize, SM1);
    cudaFuncSetAttribute((const void*)tgemm_kernel<1, true,  false, false, true>,
                         cudaFuncAttributeMaxDynamicSharedMemorySize, SM1);
    cudaFuncSetAttribute((const void*)tgemm_kernel<2, true,  false, true,  false>,
                         cudaFuncAttributeMaxDynamicSharedMemorySize, SM2);

    // 1) prep: weight prepacks + x->fp16
    prep_kernel<<<(PREP_TOTAL + 255) / 256, 256>>>(
        w_reduce, w_offset, w_dcnw, w_dcnh, w_expand, x,
        wpR, wpO, wpW, wpH, wpE, xp);

    // 2) xr = reduce(x): 2-pass (3 chunks); emits xrp fp16
    tgemm_kernel<2, false, true, false, false><<<dim3(72, 1, B), 256, SM2>>>(
        xp, (size_t)192 * HW, nullptr, nullptr, nullptr,
        wpR, 3, b_reduce, 180, nullptr, 0, xrp, FSTR,
        nullptr, nullptr, nullptr, nullptr);

    // 3) pack duplicated-pixel gather tensor
    pack_xrd_kernel<<<(B * G * 5 * XDE + 255) / 256, 256>>>(xrp, xrd);

    // 4) offs = offset(xr): 1-pass (3 chunks), f32 out
    tgemm_kernel<1, true, false, false, false><<<dim3(72, 2, B), 256, SM1>>>(
        xrp, FSTR, nullptr, nullptr, nullptr,
        wpO, 3, b_offset, 360, offs, OSTR, nullptr, 0,
        nullptr, nullptr, nullptr, nullptr);

    // 5) im2col -> fp16 col planes (conv split across grid.z)
    im2col_kernel<<<dim3(HW / 512, G, 2 * B), 256>>>(xrd, offs, cw, ch);

    // 6) BOTH deform GEMMs in one launch: 1-pass (26 chunks), f32 out
    tgemm_kernel<1, true, false, false, true><<<dim3(72, 1, 2 * B), 256, SM1>>>(
        cw, CSTR, nullptr, nullptr, nullptr,
        wpW, 26, b_dcnw, 180, fw, FSTR, nullptr, 0,
        ch, wpH, b_dcnh, fh);

    // 7) attention
    reduce_mean_kernel<<<B * CMID, 256>>>(fw, fh, avg);
    attn_kernel<<<1, 64>>>(avg, w_attn, b_attn, attn);

    // 8) out = expand(attn0*f_h + attn1*f_w): 2-pass (3 chunks), mix fused
    tgemm_kernel<2, true, false, true, false><<<dim3(72, 1, B), 256, SM2>>>(
        nullptr, FSTR, fh, fw, attn,
        wpE, 3, b_expand, 192, out, (size_t)CIN * HW, nullptr, 0,
        nullptr, nullptr, nullptr, nullptr);
}